// round 5
// baseline (speedup 1.0000x reference)
#include <cuda_runtime.h>
#include <stdint.h>
#include <math.h>

#define B_ROWS 16384
#define N_G    8192
#define D      256
#define MT     128
#define NTile  128
#define NTILES (N_G / NTile)        // 64
#define NCHUNK (NTILES * 4)         // 256 -> chunks of K=64; 4 per tile

#define STRB   68                   // floats per B row (64 data + 4 pad)

#define AFRAG_BYTES 131072          // 32 kk x 4 wm x 2 mt x 32 lane x 16B
#define BSTAGE      (MT * STRB * 4) // 34816
#define SM_BS       AFRAG_BYTES
#define SM_TOP      (SM_BS + 2 * BSTAGE)   // 200704
#define SM_WIN      (SM_TOP + 4096)
#define SMEM_TOTAL  (SM_WIN + 512)         // 205312

// ---------------- device scratch ----------------
__device__ float        d_gt[N_G * D];      // tf32-valued normalized g
__device__ float        d_rnorm[N_G];
__device__ float        d_sums[N_G * D];
__device__ unsigned int d_counts[N_G];

// ---------------- helpers ----------------
__device__ __forceinline__ uint32_t smem_u32(const void* p) {
    uint32_t a;
    asm("{ .reg .u64 t; cvta.to.shared.u64 t, %1; cvt.u32.u64 %0, t; }" : "=r"(a) : "l"(p));
    return a;
}
__device__ __forceinline__ float to_tf32(float v) {
    uint32_t r;
    asm("cvt.rna.tf32.f32 %0, %1;" : "=r"(r) : "f"(v));
    return __uint_as_float(r);
}
__device__ __forceinline__ void mma_tf32(float c[4], const uint32_t a[4], const uint32_t b[2]) {
    asm volatile(
        "mma.sync.aligned.m16n8k8.row.col.f32.tf32.tf32.f32 "
        "{%0,%1,%2,%3}, {%4,%5,%6,%7}, {%8,%9}, {%0,%1,%2,%3};"
        : "+f"(c[0]), "+f"(c[1]), "+f"(c[2]), "+f"(c[3])
        : "r"(a[0]), "r"(a[1]), "r"(a[2]), "r"(a[3]), "r"(b[0]), "r"(b[1]));
}
__device__ __forceinline__ void top2_merge(float& b1, int& i1, float& s1, int& j1,
                                           float b2, int i2, float s2, int j2) {
    if (b2 > b1 || (b2 == b1 && i2 < i1)) {
        float cs; int cj;
        if (b1 > s2 || (b1 == s2 && i1 < j2)) { cs = b1; cj = i1; } else { cs = s2; cj = j2; }
        b1 = b2; i1 = i2; s1 = cs; j1 = cj;
    } else if (b2 > s1 || (b2 == s1 && i2 < j1)) {
        s1 = b2; j1 = i2;
    }
}

// ---------------------------------------------------------------------------
// prep: normalize g -> tf32; zero sums/counts; keep rnorm
// ---------------------------------------------------------------------------
__global__ void __launch_bounds__(256) prep_g_kernel(const float* __restrict__ gf) {
    int g = blockIdx.x;
    int t = threadIdx.x;
    float v = gf[g * D + t];
    d_sums[g * D + t] = 0.0f;

    float s = v * v;
    #pragma unroll
    for (int o = 16; o; o >>= 1) s += __shfl_xor_sync(0xFFFFFFFFu, s, o);
    __shared__ float red[8];
    __shared__ float srn;
    if ((t & 31) == 0) red[t >> 5] = s;
    __syncthreads();
    if (t < 8) {
        float r = red[t];
        #pragma unroll
        for (int o = 4; o; o >>= 1) r += __shfl_xor_sync(0xFFu, r, o);
        if (t == 0) {
            float rn = 1.0f / fmaxf(sqrtf(r), 1e-12f);
            srn = rn;
            d_rnorm[g] = rn;
            d_counts[g] = 0u;
        }
    }
    __syncthreads();
    d_gt[g * D + t] = to_tf32(v * srn);
}

// ---------------------------------------------------------------------------
// main: tf32 mma.sync GEMM (fragment-packed A) + top-2 argmax + repair + scatter
// ---------------------------------------------------------------------------
__global__ void __launch_bounds__(256, 1)
assign_kernel(const float* __restrict__ x, const float* __restrict__ gf) {
    extern __shared__ char smem[];
    float4* Afrag = (float4*)smem;                 // [32 kk][4 wm][2 mt][32 lane]
    float*  Bs    = (float*)(smem + SM_BS);        // [2][128][68]
    float*  tb_s  = (float*)(smem + SM_TOP);
    float*  ts_s  = tb_s + 256;
    int*    tbi_s = (int*)(ts_s + 256);
    int*    tsi_s = tbi_s + 256;
    int*    swin  = (int*)(smem + SM_WIN);

    const int tid  = threadIdx.x;
    const int wid  = tid >> 5;
    const int lane = tid & 31;
    const int wm   = wid >> 1;
    const int wn   = wid & 1;
    const int l4   = lane >> 2;
    const int lq   = lane & 3;
    const int bm   = blockIdx.x * MT;

    // ---- build fragment-packed A from global x (fused tf32 convert) ----
    for (int i = tid; i < 32 * 256; i += 256) {
        int ls = i & 31, mts = (i >> 5) & 1, wms = (i >> 6) & 3, kk = i >> 8;
        int r = wms * 32 + mts * 16 + (ls >> 2);
        int c = kk * 8 + (ls & 3);
        const float* x0 = x + (size_t)(bm + r) * D;
        const float* x8 = x0 + 8 * D;
        float4 v;
        v.x = to_tf32(x0[c]);
        v.y = to_tf32(x8[c]);
        v.z = to_tf32(x0[c + 4]);
        v.w = to_tf32(x8[c + 4]);
        Afrag[i] = v;
    }

    // ---- B prefetch: chunk t = (tile = t>>2, kc4 = t&3), buf = t&1 ----
    const int nrow = tid >> 1;          // 0..127
    const int half = tid & 1;
    auto prefetchB = [&](int t) {
        int tile = t >> 2, kc4 = t & 3;
        const float* src = &d_gt[(size_t)(tile * NTile + nrow) * D + kc4 * 64 + half * 32];
        uint32_t dst = smem_u32(&Bs[(t & 1) * (MT * STRB) + nrow * STRB + half * 32]);
        #pragma unroll
        for (int q = 0; q < 8; q++)
            asm volatile("cp.async.cg.shared.global [%0], [%1], 16;"
                         :: "r"(dst + q * 16), "l"(src + q * 4));
    };

    prefetchB(0);
    asm volatile("cp.async.commit_group;");
    __syncthreads();      // Afrag ready (also covers first-stage ordering)

    float C[2][8][4];
    float tb[2][2], ts[2][2];
    int   tbi[2][2], tsi[2][2];
    #pragma unroll
    for (int mt = 0; mt < 2; mt++)
        #pragma unroll
        for (int h = 0; h < 2; h++) {
            tb[mt][h] = -1e30f; ts[mt][h] = -1e30f;
            tbi[mt][h] = 0;     tsi[mt][h] = 1;
        }

    for (int t = 0; t < NCHUNK; ++t) {
        const int tile = t >> 2, kc4 = t & 3;

        if (t + 1 < NCHUNK) prefetchB(t + 1);
        asm volatile("cp.async.commit_group;");
        asm volatile("cp.async.wait_group 1;");
        __syncthreads();

        if (kc4 == 0) {
            #pragma unroll
            for (int mt = 0; mt < 2; mt++)
                #pragma unroll
                for (int nt = 0; nt < 8; nt++)
                    #pragma unroll
                    for (int r = 0; r < 4; r++) C[mt][nt][r] = 0.0f;
        }

        const float*  Bbuf = &Bs[(t & 1) * (MT * STRB)];
        const float4* Af   = &Afrag[(size_t)kc4 * 8 * 256];

        #pragma unroll
        for (int s8 = 0; s8 < 8; s8++) {
            uint32_t a[2][4];
            #pragma unroll
            for (int mt = 0; mt < 2; mt++) {
                float4 av = Af[s8 * 256 + wm * 64 + mt * 32 + lane];
                a[mt][0] = __float_as_uint(av.x);
                a[mt][1] = __float_as_uint(av.y);
                a[mt][2] = __float_as_uint(av.z);
                a[mt][3] = __float_as_uint(av.w);
            }
            uint32_t b[8][2];
            const int kk = s8 * 8 + lq;
            #pragma unroll
            for (int nt = 0; nt < 8; nt++) {
                int n = wn * 64 + nt * 8 + l4;
                b[nt][0] = __float_as_uint(Bbuf[n * STRB + kk]);
                b[nt][1] = __float_as_uint(Bbuf[n * STRB + kk + 4]);
            }
            #pragma unroll
            for (int mt = 0; mt < 2; mt++)
                #pragma unroll
                for (int nt = 0; nt < 8; nt++)
                    mma_tf32(C[mt][nt], a[mt], b[nt]);
        }

        if (kc4 == 3) {
            const int bn = tile * NTile;
            #pragma unroll
            for (int nt = 0; nt < 8; nt++) {
                const int n0 = bn + wn * 64 + nt * 8 + 2 * lq;
                #pragma unroll
                for (int mt = 0; mt < 2; mt++)
                    #pragma unroll
                    for (int h = 0; h < 2; h++) {
                        float v0 = C[mt][nt][2 * h];
                        float v1 = C[mt][nt][2 * h + 1];
                        if (v0 > tb[mt][h]) { ts[mt][h] = tb[mt][h]; tsi[mt][h] = tbi[mt][h];
                                              tb[mt][h] = v0; tbi[mt][h] = n0; }
                        else if (v0 > ts[mt][h]) { ts[mt][h] = v0; tsi[mt][h] = n0; }
                        if (v1 > tb[mt][h]) { ts[mt][h] = tb[mt][h]; tsi[mt][h] = tbi[mt][h];
                                              tb[mt][h] = v1; tbi[mt][h] = n0 + 1; }
                        else if (v1 > ts[mt][h]) { ts[mt][h] = v1; tsi[mt][h] = n0 + 1; }
                    }
            }
        }
        __syncthreads();    // all warps done with buf t&1 before t+2 prefetch
    }

    // ---- cross-lane top-2 reduction within quads ----
    #pragma unroll
    for (int mt = 0; mt < 2; mt++)
        #pragma unroll
        for (int h = 0; h < 2; h++) {
            float b = tb[mt][h], s = ts[mt][h];
            int   bi = tbi[mt][h], si = tsi[mt][h];
            #pragma unroll
            for (int off = 1; off <= 2; off <<= 1) {
                float ob  = __shfl_xor_sync(0xFFFFFFFFu, b, off);
                float os  = __shfl_xor_sync(0xFFFFFFFFu, s, off);
                int   obi = __shfl_xor_sync(0xFFFFFFFFu, bi, off);
                int   osi = __shfl_xor_sync(0xFFFFFFFFu, si, off);
                top2_merge(b, bi, s, si, ob, obi, os, osi);
            }
            if (lq == 0) {
                int row = wm * 32 + mt * 16 + h * 8 + l4;
                int idx = row * 2 + wn;
                tb_s[idx] = b; ts_s[idx] = s; tbi_s[idx] = bi; tsi_s[idx] = si;
            }
        }
    __syncthreads();

    // ---- per-row merge + exact fp32 repair + winner ----
    if (tid < MT) {
        float b = tb_s[tid * 2], s = ts_s[tid * 2];
        int   bi = tbi_s[tid * 2], si = tsi_s[tid * 2];
        top2_merge(b, bi, s, si, tb_s[tid * 2 + 1], tbi_s[tid * 2 + 1],
                   ts_s[tid * 2 + 1], tsi_s[tid * 2 + 1]);

        if (b - s < 3e-2f) {
            const float* xr = x  + (size_t)(bm + tid) * D;
            const float* ga = gf + (size_t)bi * D;
            const float* gb = gf + (size_t)si * D;
            float va = 0.0f, vb = 0.0f;
            #pragma unroll 8
            for (int k = 0; k < D; k++) {
                float xv = xr[k];
                va = fmaf(xv, ga[k], va);
                vb = fmaf(xv, gb[k], vb);
            }
            va *= d_rnorm[bi];
            vb *= d_rnorm[si];
            if (vb > va || (vb == va && si < bi)) bi = si;
        }
        swin[tid] = bi;
        atomicAdd(&d_counts[bi], 1u);
    }
    __syncthreads();

    // ---- segment-sum scatter ----
    for (int r = 0; r < MT; r++) {
        int g = swin[r];
        atomicAdd(&d_sums[(size_t)g * D + tid], x[(size_t)(bm + r) * D + tid]);
    }
}

// ---------------------------------------------------------------------------
__global__ void __launch_bounds__(256) finalize_kernel(const float* __restrict__ gf,
                                                       float* __restrict__ out) {
    int i = blockIdx.x * 256 + threadIdx.x;
    int g = i >> 8;
    unsigned int c = d_counts[g];
    float cnt = (float)(c > 1u ? c : 1u);
    out[i] = 0.99f * gf[i] + 0.01f * (d_sums[i] / cnt);
}

// ---------------------------------------------------------------------------
extern "C" void kernel_launch(void* const* d_in, const int* in_sizes, int n_in,
                              void* d_out, int out_size) {
    const float* x;
    const float* gf;
    if (in_sizes[0] == B_ROWS * D) {
        x  = (const float*)d_in[0];
        gf = (const float*)d_in[1];
    } else {
        x  = (const float*)d_in[1];
        gf = (const float*)d_in[0];
    }
    float* out = (float*)d_out;

    cudaFuncSetAttribute(assign_kernel, cudaFuncAttributeMaxDynamicSharedMemorySize, SMEM_TOTAL);

    prep_g_kernel<<<N_G, 256>>>(gf);
    assign_kernel<<<B_ROWS / MT, 256, SMEM_TOTAL>>>(x, gf);
    finalize_kernel<<<(N_G * D) / 256, 256>>>(gf, out);
}

// round 7
// speedup vs baseline: 1.6804x; 1.6804x over previous
#include <cuda_runtime.h>
#include <cuda_bf16.h>
#include <stdint.h>
#include <math.h>

#define B_ROWS 16384
#define N_G    8192
#define D      256
#define MT     128
#define NTile  128
#define NTILES (N_G / NTile)        // 64
#define NCHUNK (NTILES * 4)         // 256 chunks of K=64

#define STRA   264                  // halves per A row (256 + 8 pad) -> 132 words
#define STRB   72                   // halves per B row (64 + 8 pad)  -> 36 words

#define SM_A_BYTES (MT * STRA * 2)              // 67584
#define B_STAGE    (NTile * STRB * 2)           // 18432
#define SM_BS      SM_A_BYTES
#define SM_TOP     (SM_BS + 2 * B_STAGE)        // 104448
#define SM_WIN     (SM_TOP + 4096)
#define SMEM_TOTAL (SM_WIN + 512)               // 109056

// ---------------- device scratch ----------------
__device__ __nv_bfloat16 d_gb[N_G * D];     // normalized g, bf16
__device__ float         d_rnorm[N_G];
__device__ float         d_sums[N_G * D];
__device__ unsigned int  d_counts[N_G];

// ---------------- helpers ----------------
__device__ __forceinline__ uint32_t smem_u32(const void* p) {
    uint32_t a;
    asm("{ .reg .u64 t; cvta.to.shared.u64 t, %1; cvt.u32.u64 %0, t; }" : "=r"(a) : "l"(p));
    return a;
}
__device__ __forceinline__ uint32_t pack_bf2(float lo, float hi) {
    uint32_t r;
    asm("cvt.rn.bf16x2.f32 %0, %1, %2;" : "=r"(r) : "f"(hi), "f"(lo));
    return r;
}
__device__ __forceinline__ void mma_bf16(float c[4], const uint32_t a[4], const uint32_t b[2]) {
    asm volatile(
        "mma.sync.aligned.m16n8k16.row.col.f32.bf16.bf16.f32 "
        "{%0,%1,%2,%3}, {%4,%5,%6,%7}, {%8,%9}, {%0,%1,%2,%3};"
        : "+f"(c[0]), "+f"(c[1]), "+f"(c[2]), "+f"(c[3])
        : "r"(a[0]), "r"(a[1]), "r"(a[2]), "r"(a[3]), "r"(b[0]), "r"(b[1]));
}
__device__ __forceinline__ void top2_merge(float& b1, int& i1, float& s1, int& j1,
                                           float b2, int i2, float s2, int j2) {
    if (b2 > b1 || (b2 == b1 && i2 < i1)) {
        float cs; int cj;
        if (b1 > s2 || (b1 == s2 && i1 < j2)) { cs = b1; cj = i1; } else { cs = s2; cj = j2; }
        b1 = b2; i1 = i2; s1 = cs; j1 = cj;
    } else if (b2 > s1 || (b2 == s1 && i2 < j1)) {
        s1 = b2; j1 = i2;
    }
}

// ---------------------------------------------------------------------------
// prep: normalize g -> bf16; zero sums/counts; keep rnorm
// ---------------------------------------------------------------------------
__global__ void __launch_bounds__(256) prep_g_kernel(const float* __restrict__ gf) {
    int g = blockIdx.x;
    int t = threadIdx.x;
    float v = gf[g * D + t];
    d_sums[g * D + t] = 0.0f;

    float s = v * v;
    #pragma unroll
    for (int o = 16; o; o >>= 1) s += __shfl_xor_sync(0xFFFFFFFFu, s, o);
    __shared__ float red[8];
    __shared__ float srn;
    if ((t & 31) == 0) red[t >> 5] = s;
    __syncthreads();
    if (t < 8) {
        float r = red[t];
        #pragma unroll
        for (int o = 4; o; o >>= 1) r += __shfl_xor_sync(0xFFu, r, o);
        if (t == 0) {
            float rn = 1.0f / fmaxf(sqrtf(r), 1e-12f);
            srn = rn;
            d_rnorm[g] = rn;
            d_counts[g] = 0u;
        }
    }
    __syncthreads();
    d_gb[g * D + t] = __float2bfloat16(v * srn);
}

// ---------------------------------------------------------------------------
// main: bf16 m16n8k16 GEMM + top-2 argmax + fp32 repair + segment-sum
//   128 CTAs x 256 thr; 8 warps 4(M)x2(N); warp tile 32x64
// ---------------------------------------------------------------------------
__global__ void __launch_bounds__(256, 1)
assign_kernel(const float* __restrict__ x, const float* __restrict__ gf) {
    extern __shared__ char smem[];
    char*  As    = smem;                          // [128][264] bf16
    char*  Bs    = smem + SM_BS;                  // [2][128][72] bf16
    float* tb_s  = (float*)(smem + SM_TOP);
    float* ts_s  = tb_s + 256;
    int*   tbi_s = (int*)(ts_s + 256);
    int*   tsi_s = tbi_s + 256;
    int*   swin  = (int*)(smem + SM_WIN);

    const int tid  = threadIdx.x;
    const int lane = tid & 31;
    const int wid  = tid >> 5;
    const int wm   = wid >> 1;
    const int wn   = wid & 1;
    const int l4   = lane >> 2;
    const int lq   = lane & 3;
    const int bm   = blockIdx.x * MT;

    // ---- build A in SMEM (fused fp32->bf16 convert): thread i covers float4 ----
    for (int i = tid; i < MT * 64; i += 256) {
        int m = i >> 6, q = i & 63;
        float4 v = *(const float4*)&x[(size_t)(bm + m) * D + q * 4];
        uint2 p;
        p.x = pack_bf2(v.x, v.y);
        p.y = pack_bf2(v.z, v.w);
        *(uint2*)(As + m * (STRA * 2) + q * 8) = p;
    }

    // ---- B prefetch: chunk t = (tile=t>>2, kc=t&3), stage t&1 ----
    const int nrow = tid >> 1;          // 0..127
    const int half = tid & 1;           // 0..1
    auto prefetchB = [&](int t) {
        int tile = t >> 2, kc = t & 3;
        const __nv_bfloat16* src =
            &d_gb[(size_t)(tile * NTile + nrow) * D + kc * 64 + half * 32];
        uint32_t dst = smem_u32(Bs + (t & 1) * B_STAGE + nrow * (STRB * 2) + half * 64);
        #pragma unroll
        for (int q = 0; q < 4; q++)
            asm volatile("cp.async.cg.shared.global [%0], [%1], 16;"
                         :: "r"(dst + q * 16), "l"(src + q * 8));
    };

    prefetchB(0);
    asm volatile("cp.async.commit_group;");
    __syncthreads();

    float C[2][8][4];
    float tb[2][2], ts[2][2];
    int   tbi[2][2], tsi[2][2];
    #pragma unroll
    for (int mt = 0; mt < 2; mt++)
        #pragma unroll
        for (int h = 0; h < 2; h++) {
            tb[mt][h] = -1e30f; ts[mt][h] = -1e30f;
            tbi[mt][h] = 0;     tsi[mt][h] = 1;
        }

    for (int t = 0; t < NCHUNK; ++t) {
        const int tile = t >> 2, kc = t & 3;

        if (t + 1 < NCHUNK) prefetchB(t + 1);
        asm volatile("cp.async.commit_group;");
        asm volatile("cp.async.wait_group 1;");
        __syncthreads();

        if (kc == 0) {
            #pragma unroll
            for (int mt = 0; mt < 2; mt++)
                #pragma unroll
                for (int nt = 0; nt < 8; nt++)
                    #pragma unroll
                    for (int r = 0; r < 4; r++) C[mt][nt][r] = 0.0f;
        }

        const char* Bbuf = Bs + (t & 1) * B_STAGE;

        #pragma unroll
        for (int s = 0; s < 4; s++) {
            const int k0 = kc * 64 + s * 16;       // column base into A
            const int ks = s * 16;                 // column base into B stage
            uint32_t a[2][4];
            #pragma unroll
            for (int mt = 0; mt < 2; mt++) {
                int r = wm * 32 + mt * 16 + l4;
                const char* base = As + r * (STRA * 2) + (k0 + 2 * lq) * 2;
                a[mt][0] = *(const uint32_t*)(base);
                a[mt][1] = *(const uint32_t*)(base + 8 * (STRA * 2));
                a[mt][2] = *(const uint32_t*)(base + 16);
                a[mt][3] = *(const uint32_t*)(base + 8 * (STRA * 2) + 16);
            }
            uint32_t b[8][2];
            #pragma unroll
            for (int nt = 0; nt < 8; nt++) {
                int n = wn * 64 + nt * 8 + l4;
                const char* base = Bbuf + n * (STRB * 2) + (ks + 2 * lq) * 2;
                b[nt][0] = *(const uint32_t*)(base);
                b[nt][1] = *(const uint32_t*)(base + 16);
            }
            #pragma unroll
            for (int mt = 0; mt < 2; mt++)
                #pragma unroll
                for (int nt = 0; nt < 8; nt++)
                    mma_bf16(C[mt][nt], a[mt], b[nt]);
        }

        if (kc == 3) {
            const int bn = tile * NTile;
            #pragma unroll
            for (int nt = 0; nt < 8; nt++) {
                const int n0 = bn + wn * 64 + nt * 8 + 2 * lq;
                #pragma unroll
                for (int mt = 0; mt < 2; mt++)
                    #pragma unroll
                    for (int h = 0; h < 2; h++) {
                        float v0 = C[mt][nt][2 * h];
                        float v1 = C[mt][nt][2 * h + 1];
                        if (v0 > tb[mt][h]) { ts[mt][h] = tb[mt][h]; tsi[mt][h] = tbi[mt][h];
                                              tb[mt][h] = v0; tbi[mt][h] = n0; }
                        else if (v0 > ts[mt][h]) { ts[mt][h] = v0; tsi[mt][h] = n0; }
                        if (v1 > tb[mt][h]) { ts[mt][h] = tb[mt][h]; tsi[mt][h] = tbi[mt][h];
                                              tb[mt][h] = v1; tbi[mt][h] = n0 + 1; }
                        else if (v1 > ts[mt][h]) { ts[mt][h] = v1; tsi[mt][h] = n0 + 1; }
                    }
            }
        }
        __syncthreads();
    }

    // ---- cross-lane top-2 reduction within quads ----
    #pragma unroll
    for (int mt = 0; mt < 2; mt++)
        #pragma unroll
        for (int h = 0; h < 2; h++) {
            float b = tb[mt][h], s = ts[mt][h];
            int   bi = tbi[mt][h], si = tsi[mt][h];
            #pragma unroll
            for (int off = 1; off <= 2; off <<= 1) {
                float ob  = __shfl_xor_sync(0xFFFFFFFFu, b, off);
                float os  = __shfl_xor_sync(0xFFFFFFFFu, s, off);
                int   obi = __shfl_xor_sync(0xFFFFFFFFu, bi, off);
                int   osi = __shfl_xor_sync(0xFFFFFFFFu, si, off);
                top2_merge(b, bi, s, si, ob, obi, os, osi);
            }
            if (lq == 0) {
                int row = wm * 32 + mt * 16 + h * 8 + l4;
                int idx = row * 2 + wn;
                tb_s[idx] = b; ts_s[idx] = s; tbi_s[idx] = bi; tsi_s[idx] = si;
            }
        }
    __syncthreads();

    // ---- per-row merge + exact fp32 repair + winner ----
    if (tid < MT) {
        float b = tb_s[tid * 2], s = ts_s[tid * 2];
        int   bi = tbi_s[tid * 2], si = tsi_s[tid * 2];
        top2_merge(b, bi, s, si, tb_s[tid * 2 + 1], tbi_s[tid * 2 + 1],
                   ts_s[tid * 2 + 1], tsi_s[tid * 2 + 1]);

        if (b - s < 1e-1f) {      // bf16 logit error tail ~3e-3 -> 30x margin
            const float* xr = x  + (size_t)(bm + tid) * D;
            const float* ga = gf + (size_t)bi * D;
            const float* gb = gf + (size_t)si * D;
            float va = 0.0f, vb = 0.0f;
            #pragma unroll 8
            for (int k = 0; k < D; k++) {
                float xv = xr[k];
                va = fmaf(xv, ga[k], va);
                vb = fmaf(xv, gb[k], vb);
            }
            va *= d_rnorm[bi];
            vb *= d_rnorm[si];
            if (vb > va || (vb == va && si < bi)) bi = si;
        }
        swin[tid] = bi;
        atomicAdd(&d_counts[bi], 1u);
    }
    __syncthreads();

    // ---- segment-sum scatter: each thread owns one dim ----
    for (int r = 0; r < MT; r++) {
        int g = swin[r];
        atomicAdd(&d_sums[(size_t)g * D + tid], x[(size_t)(bm + r) * D + tid]);
    }
}

// ---------------------------------------------------------------------------
__global__ void __launch_bounds__(256) finalize_kernel(const float* __restrict__ gf,
                                                       float* __restrict__ out) {
    int i = blockIdx.x * 256 + threadIdx.x;
    int g = i >> 8;
    unsigned int c = d_counts[g];
    float cnt = (float)(c > 1u ? c : 1u);
    out[i] = 0.99f * gf[i] + 0.01f * (d_sums[i] / cnt);
}

// ---------------------------------------------------------------------------
extern "C" void kernel_launch(void* const* d_in, const int* in_sizes, int n_in,
                              void* d_out, int out_size) {
    const float* x;
    const float* gf;
    if (in_sizes[0] == B_ROWS * D) {
        x  = (const float*)d_in[0];
        gf = (const float*)d_in[1];
    } else {
        x  = (const float*)d_in[1];
        gf = (const float*)d_in[0];
    }
    float* out = (float*)d_out;

    cudaFuncSetAttribute(assign_kernel, cudaFuncAttributeMaxDynamicSharedMemorySize, SMEM_TOTAL);

    prep_g_kernel<<<N_G, 256>>>(gf);
    assign_kernel<<<B_ROWS / MT, 256, SMEM_TOTAL>>>(x, gf);
    finalize_kernel<<<(N_G * D) / 256, 256>>>(gf, out);
}

// round 8
// speedup vs baseline: 1.6912x; 1.0064x over previous
#include <cuda_runtime.h>
#include <cuda_bf16.h>
#include <stdint.h>
#include <math.h>

#define B_ROWS 16384
#define N_G    8192
#define D      256
#define MT     128
#define NTile  128
#define NTILES (N_G / NTile)        // 64
#define NCHUNK (NTILES * 2)         // 128 chunks of K=128

#define STRA   264                  // halves per A row (256 + 8 pad) -> 132 words
#define STRB   136                  // halves per B row (128 + 8 pad) -> 68 words

#define SM_A_BYTES (MT * STRA * 2)              // 67584
#define B_STAGE    (NTile * STRB * 2)           // 34816
#define SM_BS      SM_A_BYTES
#define SM_TOP     (SM_BS + 3 * B_STAGE)        // 172032
#define SM_WIN     (SM_TOP + 4096)
#define SMEM_TOTAL (SM_WIN + 512)               // 176640

// ---------------- device scratch ----------------
__device__ __nv_bfloat16 d_gb[N_G * D];     // normalized g, bf16
__device__ float         d_rnorm[N_G];
__device__ float         d_sums[N_G * D];
__device__ unsigned int  d_counts[N_G];

// ---------------- helpers ----------------
__device__ __forceinline__ uint32_t smem_u32(const void* p) {
    uint32_t a;
    asm("{ .reg .u64 t; cvta.to.shared.u64 t, %1; cvt.u32.u64 %0, t; }" : "=r"(a) : "l"(p));
    return a;
}
__device__ __forceinline__ uint32_t pack_bf2(float lo, float hi) {
    uint32_t r;
    asm("cvt.rn.bf16x2.f32 %0, %1, %2;" : "=r"(r) : "f"(hi), "f"(lo));
    return r;
}
__device__ __forceinline__ void mma_bf16(float c[4], const uint32_t a[4], const uint32_t b[2]) {
    asm volatile(
        "mma.sync.aligned.m16n8k16.row.col.f32.bf16.bf16.f32 "
        "{%0,%1,%2,%3}, {%4,%5,%6,%7}, {%8,%9}, {%0,%1,%2,%3};"
        : "+f"(c[0]), "+f"(c[1]), "+f"(c[2]), "+f"(c[3])
        : "r"(a[0]), "r"(a[1]), "r"(a[2]), "r"(a[3]), "r"(b[0]), "r"(b[1]));
}
__device__ __forceinline__ void top2_merge(float& b1, int& i1, float& s1, int& j1,
                                           float b2, int i2, float s2, int j2) {
    if (b2 > b1 || (b2 == b1 && i2 < i1)) {
        float cs; int cj;
        if (b1 > s2 || (b1 == s2 && i1 < j2)) { cs = b1; cj = i1; } else { cs = s2; cj = j2; }
        b1 = b2; i1 = i2; s1 = cs; j1 = cj;
    } else if (b2 > s1 || (b2 == s1 && i2 < j1)) {
        s1 = b2; j1 = i2;
    }
}

// ---------------------------------------------------------------------------
// prep: normalize g -> bf16; zero sums/counts; keep rnorm
// ---------------------------------------------------------------------------
__global__ void __launch_bounds__(256) prep_g_kernel(const float* __restrict__ gf) {
    int g = blockIdx.x;
    int t = threadIdx.x;
    float v = gf[g * D + t];
    d_sums[g * D + t] = 0.0f;

    float s = v * v;
    #pragma unroll
    for (int o = 16; o; o >>= 1) s += __shfl_xor_sync(0xFFFFFFFFu, s, o);
    __shared__ float red[8];
    __shared__ float srn;
    if ((t & 31) == 0) red[t >> 5] = s;
    __syncthreads();
    if (t < 8) {
        float r = red[t];
        #pragma unroll
        for (int o = 4; o; o >>= 1) r += __shfl_xor_sync(0xFFu, r, o);
        if (t == 0) {
            float rn = 1.0f / fmaxf(sqrtf(r), 1e-12f);
            srn = rn;
            d_rnorm[g] = rn;
            d_counts[g] = 0u;
        }
    }
    __syncthreads();
    d_gb[g * D + t] = __float2bfloat16(v * srn);
}

// ---------------------------------------------------------------------------
// main: bf16 m16n8k16 GEMM, 3-stage cp.async ring, 1 barrier per K=128 chunk
// ---------------------------------------------------------------------------
__global__ void __launch_bounds__(256, 1)
assign_kernel(const float* __restrict__ x, const float* __restrict__ gf) {
    extern __shared__ char smem[];
    char*  As    = smem;                          // [128][264] bf16
    char*  Bs    = smem + SM_BS;                  // [3][128][136] bf16
    float* tb_s  = (float*)(smem + SM_TOP);
    float* ts_s  = tb_s + 256;
    int*   tbi_s = (int*)(ts_s + 256);
    int*   tsi_s = tbi_s + 256;
    int*   swin  = (int*)(smem + SM_WIN);

    const int tid  = threadIdx.x;
    const int lane = tid & 31;
    const int wid  = tid >> 5;
    const int wm   = wid >> 1;
    const int wn   = wid & 1;
    const int l4   = lane >> 2;
    const int lq   = lane & 3;
    const int bm   = blockIdx.x * MT;

    // ---- build A in SMEM (fused fp32->bf16 convert) ----
    for (int i = tid; i < MT * 64; i += 256) {
        int m = i >> 6, q = i & 63;
        float4 v = *(const float4*)&x[(size_t)(bm + m) * D + q * 4];
        uint2 p;
        p.x = pack_bf2(v.x, v.y);
        p.y = pack_bf2(v.z, v.w);
        *(uint2*)(As + m * (STRA * 2) + q * 8) = p;
    }

    // ---- B prefetch: chunk t = (tile=t>>1, kc=t&1), stage t%3 ----
    const int nrow = tid >> 1;          // 0..127
    const int half = tid & 1;           // 0..1
    auto prefetchB = [&](int t) {
        int tile = t >> 1, kc = t & 1;
        const __nv_bfloat16* src =
            &d_gb[(size_t)(tile * NTile + nrow) * D + kc * 128 + half * 64];
        uint32_t dst = smem_u32(Bs + (t % 3) * B_STAGE + nrow * (STRB * 2) + half * 128);
        #pragma unroll
        for (int q = 0; q < 8; q++)
            asm volatile("cp.async.cg.shared.global [%0], [%1], 16;"
                         :: "r"(dst + q * 16), "l"(src + q * 8));
    };

    prefetchB(0);
    asm volatile("cp.async.commit_group;");
    prefetchB(1);
    asm volatile("cp.async.commit_group;");

    float C[2][8][4];
    float tb[2][2], ts[2][2];
    int   tbi[2][2], tsi[2][2];
    #pragma unroll
    for (int mt = 0; mt < 2; mt++)
        #pragma unroll
        for (int h = 0; h < 2; h++) {
            tb[mt][h] = -1e30f; ts[mt][h] = -1e30f;
            tbi[mt][h] = 0;     tsi[mt][h] = 1;
        }

    for (int t = 0; t < NCHUNK; ++t) {
        const int tile = t >> 1, kc = t & 1;

        asm volatile("cp.async.wait_group 1;");
        __syncthreads();      // stage t ready; all warps done with stage (t-1)

        if (kc == 0) {
            #pragma unroll
            for (int mt = 0; mt < 2; mt++)
                #pragma unroll
                for (int nt = 0; nt < 8; nt++)
                    #pragma unroll
                    for (int r = 0; r < 4; r++) C[mt][nt][r] = 0.0f;
        }

        const char* Bbuf = Bs + (t % 3) * B_STAGE;

        #pragma unroll
        for (int s = 0; s < 8; s++) {
            const int k0 = kc * 128 + s * 16;      // column base into A
            const int ks = s * 16;                 // column base into B stage
            uint32_t a[2][4];
            #pragma unroll
            for (int mt = 0; mt < 2; mt++) {
                int r = wm * 32 + mt * 16 + l4;
                const char* base = As + r * (STRA * 2) + (k0 + 2 * lq) * 2;
                a[mt][0] = *(const uint32_t*)(base);
                a[mt][1] = *(const uint32_t*)(base + 8 * (STRA * 2));
                a[mt][2] = *(const uint32_t*)(base + 16);
                a[mt][3] = *(const uint32_t*)(base + 8 * (STRA * 2) + 16);
            }
            uint32_t b[8][2];
            #pragma unroll
            for (int nt = 0; nt < 8; nt++) {
                int n = wn * 64 + nt * 8 + l4;
                const char* base = Bbuf + n * (STRB * 2) + (ks + 2 * lq) * 2;
                b[nt][0] = *(const uint32_t*)(base);
                b[nt][1] = *(const uint32_t*)(base + 16);
            }
            #pragma unroll
            for (int mt = 0; mt < 2; mt++)
                #pragma unroll
                for (int nt = 0; nt < 8; nt++)
                    mma_bf16(C[mt][nt], a[mt], b[nt]);
        }

        // prefetch t+2 into the stage all warps provably released (barrier above)
        if (t + 2 < NCHUNK) prefetchB(t + 2);
        asm volatile("cp.async.commit_group;");    // commit (possibly empty) keeps group count aligned

        if (kc == 1) {
            const int bn = tile * NTile;
            #pragma unroll
            for (int nt = 0; nt < 8; nt++) {
                const int n0 = bn + wn * 64 + nt * 8 + 2 * lq;
                #pragma unroll
                for (int mt = 0; mt < 2; mt++)
                    #pragma unroll
                    for (int h = 0; h < 2; h++) {
                        float v0 = C[mt][nt][2 * h];
                        float v1 = C[mt][nt][2 * h + 1];
                        if (v0 > tb[mt][h]) { ts[mt][h] = tb[mt][h]; tsi[mt][h] = tbi[mt][h];
                                              tb[mt][h] = v0; tbi[mt][h] = n0; }
                        else if (v0 > ts[mt][h]) { ts[mt][h] = v0; tsi[mt][h] = n0; }
                        if (v1 > tb[mt][h]) { ts[mt][h] = tb[mt][h]; tsi[mt][h] = tbi[mt][h];
                                              tb[mt][h] = v1; tbi[mt][h] = n0 + 1; }
                        else if (v1 > ts[mt][h]) { ts[mt][h] = v1; tsi[mt][h] = n0 + 1; }
                    }
            }
        }
    }

    // ---- cross-lane top-2 reduction within quads ----
    #pragma unroll
    for (int mt = 0; mt < 2; mt++)
        #pragma unroll
        for (int h = 0; h < 2; h++) {
            float b = tb[mt][h], s = ts[mt][h];
            int   bi = tbi[mt][h], si = tsi[mt][h];
            #pragma unroll
            for (int off = 1; off <= 2; off <<= 1) {
                float ob  = __shfl_xor_sync(0xFFFFFFFFu, b, off);
                float os  = __shfl_xor_sync(0xFFFFFFFFu, s, off);
                int   obi = __shfl_xor_sync(0xFFFFFFFFu, bi, off);
                int   osi = __shfl_xor_sync(0xFFFFFFFFu, si, off);
                top2_merge(b, bi, s, si, ob, obi, os, osi);
            }
            if (lq == 0) {
                int row = wm * 32 + mt * 16 + h * 8 + l4;
                int idx = row * 2 + wn;
                tb_s[idx] = b; ts_s[idx] = s; tbi_s[idx] = bi; tsi_s[idx] = si;
            }
        }
    __syncthreads();

    // ---- per-row merge + exact fp32 repair + winner ----
    if (tid < MT) {
        float b = tb_s[tid * 2], s = ts_s[tid * 2];
        int   bi = tbi_s[tid * 2], si = tsi_s[tid * 2];
        top2_merge(b, bi, s, si, tb_s[tid * 2 + 1], tbi_s[tid * 2 + 1],
                   ts_s[tid * 2 + 1], tsi_s[tid * 2 + 1]);

        if (b - s < 1e-1f) {
            const float* xr = x  + (size_t)(bm + tid) * D;
            const float* ga = gf + (size_t)bi * D;
            const float* gb = gf + (size_t)si * D;
            float va = 0.0f, vb = 0.0f;
            #pragma unroll 8
            for (int k = 0; k < D; k++) {
                float xv = xr[k];
                va = fmaf(xv, ga[k], va);
                vb = fmaf(xv, gb[k], vb);
            }
            va *= d_rnorm[bi];
            vb *= d_rnorm[si];
            if (vb > va || (vb == va && si < bi)) bi = si;
        }
        swin[tid] = bi;
        atomicAdd(&d_counts[bi], 1u);
    }
    __syncthreads();

    // ---- segment-sum scatter ----
    for (int r = 0; r < MT; r++) {
        int g = swin[r];
        atomicAdd(&d_sums[(size_t)g * D + tid], x[(size_t)(bm + r) * D + tid]);
    }
}

// ---------------------------------------------------------------------------
__global__ void __launch_bounds__(256) finalize_kernel(const float* __restrict__ gf,
                                                       float* __restrict__ out) {
    int i = blockIdx.x * 256 + threadIdx.x;
    int g = i >> 8;
    unsigned int c = d_counts[g];
    float cnt = (float)(c > 1u ? c : 1u);
    out[i] = 0.99f * gf[i] + 0.01f * (d_sums[i] / cnt);
}

// ---------------------------------------------------------------------------
extern "C" void kernel_launch(void* const* d_in, const int* in_sizes, int n_in,
                              void* d_out, int out_size) {
    const float* x;
    const float* gf;
    if (in_sizes[0] == B_ROWS * D) {
        x  = (const float*)d_in[0];
        gf = (const float*)d_in[1];
    } else {
        x  = (const float*)d_in[1];
        gf = (const float*)d_in[0];
    }
    float* out = (float*)d_out;

    cudaFuncSetAttribute(assign_kernel, cudaFuncAttributeMaxDynamicSharedMemorySize, SMEM_TOTAL);

    prep_g_kernel<<<N_G, 256>>>(gf);
    assign_kernel<<<B_ROWS / MT, 256, SMEM_TOTAL>>>(x, gf);
    finalize_kernel<<<(N_G * D) / 256, 256>>>(gf, out);
}

// round 9
// speedup vs baseline: 1.8301x; 1.0821x over previous
#include <cuda_runtime.h>
#include <cuda_bf16.h>
#include <stdint.h>
#include <math.h>

#define B_ROWS 16384
#define N_G    8192
#define D      256
#define MT     128
#define NTile  128
#define NTILES (N_G / NTile)        // 64
#define NCHUNK (NTILES * 2)         // 128 chunks of K=128

#define STRA   264                  // halves per A row (256 + 8 pad) -> 528 B
#define STRB   136                  // halves per B row (128 + 8 pad) -> 272 B

#define SM_A_BYTES (MT * STRA * 2)              // 67584
#define B_STAGE    (NTile * STRB * 2)           // 34816
#define SM_BS      SM_A_BYTES
#define SM_TOP     (SM_BS + 3 * B_STAGE)        // 172032
#define SM_WIN     (SM_TOP + 4096)
#define SMEM_TOTAL (SM_WIN + 512)               // 176640

// ---------------- device scratch ----------------
__device__ __nv_bfloat16 d_gb[N_G * D];     // normalized g, bf16
__device__ float         d_rnorm[N_G];
__device__ float         d_sums[N_G * D];
__device__ unsigned int  d_counts[N_G];

// ---------------- helpers ----------------
__device__ __forceinline__ uint32_t smem_u32(const void* p) {
    uint32_t a;
    asm("{ .reg .u64 t; cvta.to.shared.u64 t, %1; cvt.u32.u64 %0, t; }" : "=r"(a) : "l"(p));
    return a;
}
__device__ __forceinline__ uint32_t pack_bf2(float lo, float hi) {
    uint32_t r;
    asm("cvt.rn.bf16x2.f32 %0, %1, %2;" : "=r"(r) : "f"(hi), "f"(lo));
    return r;
}
__device__ __forceinline__ void ldm_x4(uint32_t r[4], uint32_t addr) {
    asm volatile("ldmatrix.sync.aligned.m8n8.x4.shared.b16 {%0,%1,%2,%3}, [%4];"
                 : "=r"(r[0]), "=r"(r[1]), "=r"(r[2]), "=r"(r[3]) : "r"(addr));
}
__device__ __forceinline__ void mma_bf16(float c[4], const uint32_t a[4], const uint32_t b[2]) {
    asm volatile(
        "mma.sync.aligned.m16n8k16.row.col.f32.bf16.bf16.f32 "
        "{%0,%1,%2,%3}, {%4,%5,%6,%7}, {%8,%9}, {%0,%1,%2,%3};"
        : "+f"(c[0]), "+f"(c[1]), "+f"(c[2]), "+f"(c[3])
        : "r"(a[0]), "r"(a[1]), "r"(a[2]), "r"(a[3]), "r"(b[0]), "r"(b[1]));
}
__device__ __forceinline__ void top2_merge(float& b1, int& i1, float& s1, int& j1,
                                           float b2, int i2, float s2, int j2) {
    if (b2 > b1 || (b2 == b1 && i2 < i1)) {
        float cs; int cj;
        if (b1 > s2 || (b1 == s2 && i1 < j2)) { cs = b1; cj = i1; } else { cs = s2; cj = j2; }
        b1 = b2; i1 = i2; s1 = cs; j1 = cj;
    } else if (b2 > s1 || (b2 == s1 && i2 < j1)) {
        s1 = b2; j1 = i2;
    }
}

// ---------------------------------------------------------------------------
// prep: normalize g -> bf16; zero sums/counts; keep rnorm
// ---------------------------------------------------------------------------
__global__ void __launch_bounds__(256) prep_g_kernel(const float* __restrict__ gf) {
    int g = blockIdx.x;
    int t = threadIdx.x;
    float v = gf[g * D + t];
    d_sums[g * D + t] = 0.0f;

    float s = v * v;
    #pragma unroll
    for (int o = 16; o; o >>= 1) s += __shfl_xor_sync(0xFFFFFFFFu, s, o);
    __shared__ float red[8];
    __shared__ float srn;
    if ((t & 31) == 0) red[t >> 5] = s;
    __syncthreads();
    if (t < 8) {
        float r = red[t];
        #pragma unroll
        for (int o = 4; o; o >>= 1) r += __shfl_xor_sync(0xFFu, r, o);
        if (t == 0) {
            float rn = 1.0f / fmaxf(sqrtf(r), 1e-12f);
            srn = rn;
            d_rnorm[g] = rn;
            d_counts[g] = 0u;
        }
    }
    __syncthreads();
    d_gb[g * D + t] = __float2bfloat16(v * srn);
}

// ---------------------------------------------------------------------------
// main: bf16 m16n8k16 GEMM with ldmatrix.x4 fragment loads
//   128 CTAs x 256 thr; 8 warps 4(M)x2(N); warp tile 32x64
// ---------------------------------------------------------------------------
__global__ void __launch_bounds__(256, 1)
assign_kernel(const float* __restrict__ x, const float* __restrict__ gf) {
    extern __shared__ char smem[];
    char*  As    = smem;                          // [128][264] bf16
    char*  Bs    = smem + SM_BS;                  // [3][128][136] bf16
    float* tb_s  = (float*)(smem + SM_TOP);
    float* ts_s  = tb_s + 256;
    int*   tbi_s = (int*)(ts_s + 256);
    int*   tsi_s = tbi_s + 256;
    int*   swin  = (int*)(smem + SM_WIN);

    const int tid  = threadIdx.x;
    const int lane = tid & 31;
    const int wid  = tid >> 5;
    const int wm   = wid >> 1;
    const int wn   = wid & 1;
    const int l4   = lane >> 2;
    const int lq   = lane & 3;
    const int g8   = lane >> 3;        // ldmatrix lane group 0..3
    const int r8   = lane & 7;
    const int bm   = blockIdx.x * MT;

    // ---- build A in SMEM (fused fp32->bf16 convert) ----
    for (int i = tid; i < MT * 64; i += 256) {
        int m = i >> 6, q = i & 63;
        float4 v = *(const float4*)&x[(size_t)(bm + m) * D + q * 4];
        uint2 p;
        p.x = pack_bf2(v.x, v.y);
        p.y = pack_bf2(v.z, v.w);
        *(uint2*)(As + m * (STRA * 2) + q * 8) = p;
    }

    // ---- per-lane ldmatrix base addresses (row part; column added per step) ----
    // A mt-tile matrices: g8 -> {+0r,klo | +8r,klo | +0r,khi | +8r,khi}
    uint32_t aRow[2];
    #pragma unroll
    for (int mt = 0; mt < 2; mt++)
        aRow[mt] = smem_u32(As) +
                   (wm * 32 + mt * 16 + (g8 & 1) * 8 + r8) * (STRA * 2) + (g8 >> 1) * 16;
    // B pair-p matrices: g8 -> {n+0,klo | n+0,khi | n+8,klo | n+8,khi}
    uint32_t bRow[4];
    #pragma unroll
    for (int p = 0; p < 4; p++)
        bRow[p] = smem_u32(Bs) +
                  (wn * 64 + p * 16 + (g8 >> 1) * 8 + r8) * (STRB * 2) + (g8 & 1) * 16;

    // ---- B prefetch: chunk t = (tile=t>>1, kc=t&1), stage t%3 ----
    const int nrow = tid >> 1;
    const int half = tid & 1;
    auto prefetchB = [&](int t) {
        int tile = t >> 1, kc = t & 1;
        const __nv_bfloat16* src =
            &d_gb[(size_t)(tile * NTile + nrow) * D + kc * 128 + half * 64];
        uint32_t dst = smem_u32(Bs + (t % 3) * B_STAGE + nrow * (STRB * 2) + half * 128);
        #pragma unroll
        for (int q = 0; q < 8; q++)
            asm volatile("cp.async.cg.shared.global [%0], [%1], 16;"
                         :: "r"(dst + q * 16), "l"(src + q * 8));
    };

    prefetchB(0);
    asm volatile("cp.async.commit_group;");
    prefetchB(1);
    asm volatile("cp.async.commit_group;");

    float C[2][8][4];
    float tb[2][2], ts[2][2];
    int   tbi[2][2], tsi[2][2];
    #pragma unroll
    for (int mt = 0; mt < 2; mt++)
        #pragma unroll
        for (int h = 0; h < 2; h++) {
            tb[mt][h] = -1e30f; ts[mt][h] = -1e30f;
            tbi[mt][h] = 0;     tsi[mt][h] = 1;
        }

    for (int t = 0; t < NCHUNK; ++t) {
        const int tile = t >> 1, kc = t & 1;

        asm volatile("cp.async.wait_group 1;");
        __syncthreads();      // stage t ready; all warps done with stage (t-1)

        if (kc == 0) {
            #pragma unroll
            for (int mt = 0; mt < 2; mt++)
                #pragma unroll
                for (int nt = 0; nt < 8; nt++)
                    #pragma unroll
                    for (int r = 0; r < 4; r++) C[mt][nt][r] = 0.0f;
        }

        const uint32_t stoff = (t % 3) * B_STAGE;
        const uint32_t akoff = kc * 256;          // 128 cols * 2B

        #pragma unroll
        for (int s = 0; s < 8; s++) {
            uint32_t a[2][4];
            ldm_x4(a[0], aRow[0] + akoff + s * 32);
            ldm_x4(a[1], aRow[1] + akoff + s * 32);
            uint32_t b[4][4];
            #pragma unroll
            for (int p = 0; p < 4; p++)
                ldm_x4(b[p], bRow[p] + stoff + s * 32);
            #pragma unroll
            for (int mt = 0; mt < 2; mt++)
                #pragma unroll
                for (int p = 0; p < 4; p++) {
                    mma_bf16(C[mt][2 * p],     a[mt], &b[p][0]);
                    mma_bf16(C[mt][2 * p + 1], a[mt], &b[p][2]);
                }
        }

        // prefetch t+2 into the stage all warps provably released (barrier above)
        if (t + 2 < NCHUNK) prefetchB(t + 2);
        asm volatile("cp.async.commit_group;");

        if (kc == 1) {
            const int bn = tile * NTile;
            #pragma unroll
            for (int nt = 0; nt < 8; nt++) {
                const int n0 = bn + wn * 64 + nt * 8 + 2 * lq;
                #pragma unroll
                for (int mt = 0; mt < 2; mt++)
                    #pragma unroll
                    for (int h = 0; h < 2; h++) {
                        float v0 = C[mt][nt][2 * h];
                        float v1 = C[mt][nt][2 * h + 1];
                        if (v0 > tb[mt][h]) { ts[mt][h] = tb[mt][h]; tsi[mt][h] = tbi[mt][h];
                                              tb[mt][h] = v0; tbi[mt][h] = n0; }
                        else if (v0 > ts[mt][h]) { ts[mt][h] = v0; tsi[mt][h] = n0; }
                        if (v1 > tb[mt][h]) { ts[mt][h] = tb[mt][h]; tsi[mt][h] = tbi[mt][h];
                                              tb[mt][h] = v1; tbi[mt][h] = n0 + 1; }
                        else if (v1 > ts[mt][h]) { ts[mt][h] = v1; tsi[mt][h] = n0 + 1; }
                    }
            }
        }
    }

    // ---- cross-lane top-2 reduction within quads ----
    #pragma unroll
    for (int mt = 0; mt < 2; mt++)
        #pragma unroll
        for (int h = 0; h < 2; h++) {
            float b = tb[mt][h], s = ts[mt][h];
            int   bi = tbi[mt][h], si = tsi[mt][h];
            #pragma unroll
            for (int off = 1; off <= 2; off <<= 1) {
                float ob  = __shfl_xor_sync(0xFFFFFFFFu, b, off);
                float os  = __shfl_xor_sync(0xFFFFFFFFu, s, off);
                int   obi = __shfl_xor_sync(0xFFFFFFFFu, bi, off);
                int   osi = __shfl_xor_sync(0xFFFFFFFFu, si, off);
                top2_merge(b, bi, s, si, ob, obi, os, osi);
            }
            if (lq == 0) {
                int row = wm * 32 + mt * 16 + h * 8 + l4;
                int idx = row * 2 + wn;
                tb_s[idx] = b; ts_s[idx] = s; tbi_s[idx] = bi; tsi_s[idx] = si;
            }
        }
    __syncthreads();

    // ---- per-row merge + exact fp32 repair + winner ----
    if (tid < MT) {
        float b = tb_s[tid * 2], s = ts_s[tid * 2];
        int   bi = tbi_s[tid * 2], si = tsi_s[tid * 2];
        top2_merge(b, bi, s, si, tb_s[tid * 2 + 1], tbi_s[tid * 2 + 1],
                   ts_s[tid * 2 + 1], tsi_s[tid * 2 + 1]);

        if (b - s < 1e-1f) {
            const float* xr = x  + (size_t)(bm + tid) * D;
            const float* ga = gf + (size_t)bi * D;
            const float* gb = gf + (size_t)si * D;
            float va = 0.0f, vb = 0.0f;
            #pragma unroll 8
            for (int k = 0; k < D; k++) {
                float xv = xr[k];
                va = fmaf(xv, ga[k], va);
                vb = fmaf(xv, gb[k], vb);
            }
            va *= d_rnorm[bi];
            vb *= d_rnorm[si];
            if (vb > va || (vb == va && si < bi)) bi = si;
        }
        swin[tid] = bi;
        atomicAdd(&d_counts[bi], 1u);
    }
    __syncthreads();

    // ---- segment-sum scatter ----
    for (int r = 0; r < MT; r++) {
        int g = swin[r];
        atomicAdd(&d_sums[(size_t)g * D + tid], x[(size_t)(bm + r) * D + tid]);
    }
}

// ---------------------------------------------------------------------------
__global__ void __launch_bounds__(256) finalize_kernel(const float* __restrict__ gf,
                                                       float* __restrict__ out) {
    int i = blockIdx.x * 256 + threadIdx.x;
    int g = i >> 8;
    unsigned int c = d_counts[g];
    float cnt = (float)(c > 1u ? c : 1u);
    out[i] = 0.99f * gf[i] + 0.01f * (d_sums[i] / cnt);
}

// ---------------------------------------------------------------------------
extern "C" void kernel_launch(void* const* d_in, const int* in_sizes, int n_in,
                              void* d_out, int out_size) {
    const float* x;
    const float* gf;
    if (in_sizes[0] == B_ROWS * D) {
        x  = (const float*)d_in[0];
        gf = (const float*)d_in[1];
    } else {
        x  = (const float*)d_in[1];
        gf = (const float*)d_in[0];
    }
    float* out = (float*)d_out;

    cudaFuncSetAttribute(assign_kernel, cudaFuncAttributeMaxDynamicSharedMemorySize, SMEM_TOTAL);

    prep_g_kernel<<<N_G, 256>>>(gf);
    assign_kernel<<<B_ROWS / MT, 256, SMEM_TOTAL>>>(x, gf);
    finalize_kernel<<<(N_G * D) / 256, 256>>>(gf, out);
}